// round 12
// baseline (speedup 1.0000x reference)
#include <cuda_runtime.h>
#include <cuda.h>
#include <cuda_bf16.h>
#include <cstdint>
#include <dlfcn.h>

// B = 1048576 rows, C = 64, K = 4.
// out[b] = mix0*lut(s) + mix1*clip(s0+s1+s2-2,0,1) + mix2*(s0+s1+s2>=2)
// with s = x[b,:] @ softmax(cp, axis=0).
//
// Round-12: warp-autonomous streaming, 2-stage rings, 3 CTAs/SM
// (12 independent warp-streams per SM vs 8), and L2_PROMOTION_256B on the
// tensor maps for larger DRAM bursts. Testing the last two DRAM-side levers
// before declaring the ~6.1 TB/s plateau the practical ceiling.

#define NTHREADS     128
#define WARPS        4
#define WTILE_ROWS   32
#define WSTAGE_F4    512                      // 32 rows * 16 f4 = 8 KB
#define WHALF_F4     256                      // 4 KB half
#define WTILE_BYTES  8192
#define NSTAGES      2

__device__ __forceinline__ void mbar_init(void* bar, unsigned count) {
    unsigned b = (unsigned)__cvta_generic_to_shared(bar);
    asm volatile("mbarrier.init.shared.b64 [%0], %1;" :: "r"(b), "r"(count) : "memory");
}
__device__ __forceinline__ void mbar_expect_tx(void* bar, unsigned bytes) {
    unsigned b = (unsigned)__cvta_generic_to_shared(bar);
    asm volatile("mbarrier.arrive.expect_tx.shared.b64 _, [%0], %1;"
                 :: "r"(b), "r"(bytes) : "memory");
}
__device__ __forceinline__ void mbar_wait_acq(void* bar, unsigned parity) {
    unsigned b = (unsigned)__cvta_generic_to_shared(bar);
    asm volatile(
        "{\n\t"
        ".reg .pred P;\n\t"
        "WAIT_%=:\n\t"
        "mbarrier.try_wait.parity.acquire.cta.shared::cta.b64 P, [%0], %1;\n\t"
        "@!P bra WAIT_%=;\n\t"
        "}"
        :: "r"(b), "r"(parity) : "memory");
}
__device__ __forceinline__ void fence_proxy_async_cta() {
    asm volatile("fence.proxy.async.shared::cta;" ::: "memory");
}
__device__ __forceinline__ void tma_load_2d(uint32_t smem_dst, const void* tmap,
                                            int cx, int cy, void* bar) {
    unsigned b = (unsigned)__cvta_generic_to_shared(bar);
    asm volatile(
        "cp.async.bulk.tensor.2d.shared::cta.global.tile.mbarrier::complete_tx::bytes "
        "[%0], [%1, {%2, %3}], [%4];"
        :: "r"(smem_dst), "l"(tmap), "r"(cx), "r"(cy), "r"(b) : "memory");
}

extern __shared__ char g_smem_raw[];
// after 1024B alignment: [WARPS*NSTAGES*WSTAGE_F4] swizzled x | [64] probs | tail

__global__ void __launch_bounds__(NTHREADS)
lab_fused_kernel(const __grid_constant__ CUtensorMap tmapL,
                 const __grid_constant__ CUtensorMap tmapR,
                 const float* __restrict__ cp,    // [64,4]
                 const float* __restrict__ lut,   // 16
                 const float* __restrict__ mix,   // 3
                 float* __restrict__ out,
                 int nwtiles)
{
    // align tile base to the 1024B SW128 swizzle atom
    const uint32_t raw_s     = (uint32_t)__cvta_generic_to_shared(g_smem_raw);
    const uint32_t align_off = ((raw_s + 1023u) & ~1023u) - raw_s;
    char* base = g_smem_raw + align_off;

    float4* s_x     = reinterpret_cast<float4*>(base);
    float4* s_probs = s_x + WARPS * NSTAGES * WSTAGE_F4;
    float*  s_tail  = reinterpret_cast<float*>(s_probs + 64);
    float*  s_lut   = s_tail;        // 16
    float*  s_mix   = s_tail + 16;   // 3
    float*  s_inv   = s_tail + 20;   // 4
    float*  s_probs_f = reinterpret_cast<float*>(s_probs);

    __shared__ __align__(8) uint64_t s_bar[WARPS * NSTAGES];

    const int tid = threadIdx.x;

    // ---- per-block parameter prep (once) ----
    s_probs_f[tid]       = __expf(cp[tid]);
    s_probs_f[tid + 128] = __expf(cp[tid + 128]);
    if (tid < 16) s_lut[tid] = 1.0f / (1.0f + __expf(-lut[tid]));
    if (tid == 32) {
        float m0 = __expf(mix[0]), m1 = __expf(mix[1]), m2 = __expf(mix[2]);
        float inv = 1.0f / (m0 + m1 + m2);
        s_mix[0] = m0 * inv; s_mix[1] = m1 * inv; s_mix[2] = m2 * inv;
    }
    if (tid == 0) {
        #pragma unroll
        for (int i = 0; i < WARPS * NSTAGES; ++i) mbar_init(&s_bar[i], 1);
    }
    __syncthreads();
    if (tid == 0) fence_proxy_async_cta();       // order mbar init before TMA use
    __syncthreads();

    if (tid < 32) {                              // column sums: lane t sums k = t%4
        float acc = 0.0f;
        #pragma unroll
        for (int i = 0; i < 8; ++i) acc += s_probs_f[tid + 32 * i];
        #pragma unroll
        for (int off = 16; off >= 4; off >>= 1)
            acc += __shfl_down_sync(0xffffffffu, acc, off);
        if (tid < 4) s_inv[tid] = 1.0f / acc;
    }
    __syncthreads();

    s_probs_f[tid]       *= s_inv[tid & 3];      // normalize in place
    s_probs_f[tid + 128] *= s_inv[tid & 3];
    __syncthreads();                             // last CTA-wide barrier

    // ---- warp-autonomous streaming, 2-stage ring per warp ----
    const int warp = tid >> 5;
    const int lane = tid & 31;
    const int r7   = lane & 7;                   // swizzle phase of this row

    const int wstride = gridDim.x * WARPS;
    uint64_t* mybar = s_bar + warp * NSTAGES;
    const uint32_t mybase = raw_s + align_off + warp * (NSTAGES * WTILE_BYTES);
    const float4*  myx    = s_x + warp * (NSTAGES * WSTAGE_F4);

    // one warp-tile = two 4KB swizzled tensor loads (lane 0 only)
    auto load_wtile = [&](int t, int stage) {
        fence_proxy_async_cta();                 // prior LDS reads -> TMA writes
        mbar_expect_tx(&mybar[stage], WTILE_BYTES);
        uint32_t dst = mybase + stage * WTILE_BYTES;
        tma_load_2d(dst,                 &tmapL, 0, t * WTILE_ROWS, &mybar[stage]);
        tma_load_2d(dst + WHALF_F4 * 16, &tmapR, 0, t * WTILE_ROWS, &mybar[stage]);
    };

    int wt = blockIdx.x * WARPS + warp;
    if (lane == 0 && wt < nwtiles) load_wtile(wt, 0);

    int s = 0;                                   // current stage
    unsigned ph = 0;                             // per-stage parity bits
    for (; wt < nwtiles; wt += wstride) {
        // prefetch next tile into the other buffer (its reads finished last iter)
        const int nxt = wt + wstride;
        if (lane == 0 && nxt < nwtiles) load_wtile(nxt, s ^ 1);

        // wait (acquire): TMA writes of this stage visible to LDS
        mbar_wait_acq(&mybar[s], (ph >> s) & 1u);
        ph ^= (1u << s);

        // row = lane: 128B pitch per half; chunk f at index (f ^ r7)
        const float4* __restrict__ xl = myx + s * WSTAGE_F4 + lane * 8;  // f 0..7
        const float4* __restrict__ xh = xl + WHALF_F4;                   // f 8..15
        float a0 = 0.0f, a1 = 0.0f, a2 = 0.0f, a3 = 0.0f;
        #pragma unroll
        for (int f = 0; f < 16; ++f) {
            const float4 xv = (f < 8) ? xl[f ^ r7] : xh[(f - 8) ^ r7];
            const float4 p0 = s_probs[4 * f + 0];     // warp-uniform broadcast
            const float4 p1 = s_probs[4 * f + 1];
            const float4 p2 = s_probs[4 * f + 2];
            const float4 p3 = s_probs[4 * f + 3];
            a0 = fmaf(xv.x, p0.x, a0); a1 = fmaf(xv.x, p0.y, a1);
            a2 = fmaf(xv.x, p0.z, a2); a3 = fmaf(xv.x, p0.w, a3);
            a0 = fmaf(xv.y, p1.x, a0); a1 = fmaf(xv.y, p1.y, a1);
            a2 = fmaf(xv.y, p1.z, a2); a3 = fmaf(xv.y, p1.w, a3);
            a0 = fmaf(xv.z, p2.x, a0); a1 = fmaf(xv.z, p2.y, a1);
            a2 = fmaf(xv.z, p2.z, a2); a3 = fmaf(xv.z, p2.w, a3);
            a0 = fmaf(xv.w, p3.x, a0); a1 = fmaf(xv.w, p3.y, a1);
            a2 = fmaf(xv.w, p3.z, a2); a3 = fmaf(xv.w, p3.w, a3);
        }

        const float s0 = a0, s1 = a1, s2 = a2, s3 = a3;

        // addition path
        const float add = s0 + s1 + s2;
        const float ao1 = fminf(fmaxf(add - 2.0f, 0.0f), 1.0f);
        const float ao2 = (add >= 2.0f) ? 1.0f : 0.0f;

        // multilinear contraction over sigmoid(lut)[2,2,2,2]; bit0 -> s, bit1 -> 1-s
        const float w3b = 1.0f - s3;
        const float u0 = s_lut[ 0] * s3 + s_lut[ 1] * w3b;
        const float u1 = s_lut[ 2] * s3 + s_lut[ 3] * w3b;
        const float u2 = s_lut[ 4] * s3 + s_lut[ 5] * w3b;
        const float u3 = s_lut[ 6] * s3 + s_lut[ 7] * w3b;
        const float u4 = s_lut[ 8] * s3 + s_lut[ 9] * w3b;
        const float u5 = s_lut[10] * s3 + s_lut[11] * w3b;
        const float u6 = s_lut[12] * s3 + s_lut[13] * w3b;
        const float u7 = s_lut[14] * s3 + s_lut[15] * w3b;

        const float w2b = 1.0f - s2;
        const float v0 = u0 * s2 + u1 * w2b;
        const float v1 = u2 * s2 + u3 * w2b;
        const float v2 = u4 * s2 + u5 * w2b;
        const float v3 = u6 * s2 + u7 * w2b;

        const float w1b = 1.0f - s1;
        const float r0 = v0 * s1 + v1 * w1b;
        const float r1 = v2 * s1 + v3 * w1b;

        const float lut_out = r0 * s0 + r1 * (1.0f - s0);

        out[wt * WTILE_ROWS + lane] = s_mix[0] * lut_out + s_mix[1] * ao1 + s_mix[2] * ao2;

        __syncwarp();      // all lanes' reads of stage s done before it refills
        s ^= 1;
    }
}

extern "C" void kernel_launch(void* const* d_in, const int* in_sizes, int n_in,
                              void* d_out, int out_size)
{
    const float* x   = (const float*)d_in[0];   // [B, 64]
    const float* cp  = (const float*)d_in[1];   // [64, 4]
    const float* lut = (const float*)d_in[2];   // 16
    const float* mix = (const float*)d_in[3];   // 3
    float* out = (float*)d_out;

    const int B       = in_sizes[0] / 64;
    const int nwtiles = B / WTILE_ROWS;         // 32768

    // resolve cuTensorMapEncodeTiled without a -lcuda link dependency
    typedef CUresult (*EncodeFn)(CUtensorMap*, CUtensorMapDataType, cuuint32_t,
                                 void*, const cuuint64_t*, const cuuint64_t*,
                                 const cuuint32_t*, const cuuint32_t*,
                                 CUtensorMapInterleave, CUtensorMapSwizzle,
                                 CUtensorMapL2promotion, CUtensorMapFloatOOBfill);
    static EncodeFn enc = nullptr;              // host-side cache, deterministic
    if (!enc) {
        void* h = dlopen("libcuda.so.1", RTLD_NOW | RTLD_GLOBAL);
        if (!h) h = dlopen("libcuda.so", RTLD_NOW | RTLD_GLOBAL);
        enc = (EncodeFn)dlsym(h, "cuTensorMapEncodeTiled");
    }

    // two half-row descriptors: 32-float inner dim (128B = SW128 atom width),
    // row stride 256B; R half starts 128B into each row. Box = 32x32 rows (4KB).
    // 256B L2 promotion for larger DRAM bursts.
    cuuint64_t gdim[2]    = {32, (cuuint64_t)B};
    cuuint64_t gstride[1] = {256};
    cuuint32_t box[2]     = {32, WTILE_ROWS};
    cuuint32_t estr[2]    = {1, 1};

    CUtensorMap tL, tR;
    enc(&tL, CU_TENSOR_MAP_DATA_TYPE_FLOAT32, 2, (void*)x,
        gdim, gstride, box, estr,
        CU_TENSOR_MAP_INTERLEAVE_NONE, CU_TENSOR_MAP_SWIZZLE_128B,
        CU_TENSOR_MAP_L2_PROMOTION_L2_256B, CU_TENSOR_MAP_FLOAT_OOB_FILL_NONE);
    enc(&tR, CU_TENSOR_MAP_DATA_TYPE_FLOAT32, 2, (void*)((const char*)x + 128),
        gdim, gstride, box, estr,
        CU_TENSOR_MAP_INTERLEAVE_NONE, CU_TENSOR_MAP_SWIZZLE_128B,
        CU_TENSOR_MAP_L2_PROMOTION_L2_256B, CU_TENSOR_MAP_FLOAT_OOB_FILL_NONE);

    // +1KB alignment slack; 4 warps x 2 stages x 8KB; probs + tail
    const int smem_bytes = 1024 + (WARPS * NSTAGES * WSTAGE_F4 + 64) * sizeof(float4)
                         + 24 * sizeof(float);

    static bool attr_set = false;               // idempotent, host-side only
    if (!attr_set) {
        cudaFuncSetAttribute(lab_fused_kernel,
                             cudaFuncAttributeMaxDynamicSharedMemorySize, smem_bytes);
        attr_set = true;
    }

    int grid = 444;                             // 3 CTAs/SM x 148 SMs
    lab_fused_kernel<<<grid, NTHREADS, smem_bytes>>>(tL, tR, cp, lut, mix, out, nwtiles);
}

// round 13
// speedup vs baseline: 1.0877x; 1.0877x over previous
#include <cuda_runtime.h>
#include <cuda.h>
#include <cuda_bf16.h>
#include <cstdint>
#include <dlfcn.h>

// B = 1048576 rows, C = 64, K = 4.
// out[b] = mix0*lut(s) + mix1*clip(s0+s1+s2-2,0,1) + mix2*(s0+s1+s2>=2)
// with s = x[b,:] @ softmax(cp, axis=0).
//
// Round-13: best-measured config (R10: SW128 tensor-map TMA, 3-stage ring,
// prefetch distance 2, 2 CTAs/SM) + startup overlap: the initial TMA loads
// are issued BEFORE the parameter-prep chain so the first tile's DRAM
// latency hides under softmax/sigmoid prep instead of after it.
// DRAM plateau ~6.1 TB/s confirmed across 5 pipeline structures -> this is
// the converged design.

#define NTHREADS    128
#define TILE_ROWS   128
#define STAGE_F4    (TILE_ROWS * 16)          // 2048 float4 = 32 KB (L+R halves)
#define HALF_F4     (STAGE_F4 / 2)            // 1024 float4 = 16 KB
#define TILE_BYTES  (TILE_ROWS * 256)         // 32768
#define NSTAGES     3

__device__ __forceinline__ void mbar_init(void* bar, unsigned count) {
    unsigned b = (unsigned)__cvta_generic_to_shared(bar);
    asm volatile("mbarrier.init.shared.b64 [%0], %1;" :: "r"(b), "r"(count) : "memory");
}
__device__ __forceinline__ void mbar_expect_tx(void* bar, unsigned bytes) {
    unsigned b = (unsigned)__cvta_generic_to_shared(bar);
    asm volatile("mbarrier.arrive.expect_tx.shared.b64 _, [%0], %1;"
                 :: "r"(b), "r"(bytes) : "memory");
}
__device__ __forceinline__ void mbar_wait_acq(void* bar, unsigned parity) {
    unsigned b = (unsigned)__cvta_generic_to_shared(bar);
    asm volatile(
        "{\n\t"
        ".reg .pred P;\n\t"
        "WAIT_%=:\n\t"
        "mbarrier.try_wait.parity.acquire.cta.shared::cta.b64 P, [%0], %1;\n\t"
        "@!P bra WAIT_%=;\n\t"
        "}"
        :: "r"(b), "r"(parity) : "memory");
}
__device__ __forceinline__ void fence_proxy_async_cta() {
    asm volatile("fence.proxy.async.shared::cta;" ::: "memory");
}
__device__ __forceinline__ void tma_load_2d(uint32_t smem_dst, const void* tmap,
                                            int cx, int cy, void* bar) {
    unsigned b = (unsigned)__cvta_generic_to_shared(bar);
    asm volatile(
        "cp.async.bulk.tensor.2d.shared::cta.global.tile.mbarrier::complete_tx::bytes "
        "[%0], [%1, {%2, %3}], [%4];"
        :: "r"(smem_dst), "l"(tmap), "r"(cx), "r"(cy), "r"(b) : "memory");
}

extern __shared__ char g_smem_raw[];
// after 1024B alignment: [NSTAGES*STAGE_F4] swizzled x | [64] probs f4 | 24 floats

__global__ void __launch_bounds__(NTHREADS)
lab_fused_kernel(const __grid_constant__ CUtensorMap tmapL,
                 const __grid_constant__ CUtensorMap tmapR,
                 const float* __restrict__ cp,    // [64,4]
                 const float* __restrict__ lut,   // 16
                 const float* __restrict__ mix,   // 3
                 float* __restrict__ out,
                 int ntiles)
{
    // align tile base to the 1024B SW128 swizzle atom
    const uint32_t raw_s     = (uint32_t)__cvta_generic_to_shared(g_smem_raw);
    const uint32_t align_off = ((raw_s + 1023u) & ~1023u) - raw_s;
    char* base = g_smem_raw + align_off;

    float4* s_x     = reinterpret_cast<float4*>(base);          // NSTAGES stages
    float4* s_probs = s_x + NSTAGES * STAGE_F4;                 // probs[c]
    float*  s_tail  = reinterpret_cast<float*>(s_probs + 64);
    float*  s_lut   = s_tail;        // 16
    float*  s_mix   = s_tail + 16;   // 3
    float*  s_inv   = s_tail + 20;   // 4
    float*  s_probs_f = reinterpret_cast<float*>(s_probs);

    __shared__ __align__(8) uint64_t s_bar[NSTAGES];

    const int tid = threadIdx.x;
    const int stride = gridDim.x;
    const uint32_t smem_x0 = raw_s + align_off;  // 1024B-aligned

    // one tile = two 16KB swizzled tensor loads (left/right half-rows)
    auto load_tile = [&](int tile, int stage) {
        fence_proxy_async_cta();                 // prior LDS reads -> TMA writes
        mbar_expect_tx(&s_bar[stage], TILE_BYTES);
        uint32_t dst = smem_x0 + stage * (STAGE_F4 * 16);
        tma_load_2d(dst,                &tmapL, 0, tile * TILE_ROWS, &s_bar[stage]);
        tma_load_2d(dst + HALF_F4 * 16, &tmapR, 0, tile * TILE_ROWS, &s_bar[stage]);
    };

    // ---- mbarrier init FIRST, then kick off the initial TMA loads so the
    //      first tile's DRAM latency overlaps the parameter-prep chain ----
    if (tid == 0) {
        #pragma unroll
        for (int i = 0; i < NSTAGES; ++i) mbar_init(&s_bar[i], 1);
    }
    __syncthreads();                             // init visible to all / to tid0's fence

    int tile = blockIdx.x;
    if (tid == 0) {
        if (tile < ntiles)          load_tile(tile, 0);
        if (tile + stride < ntiles) load_tile(tile + stride, 1);
    }

    // ---- per-block parameter prep (overlapped with in-flight TMA) ----
    s_probs_f[tid]       = __expf(cp[tid]);
    s_probs_f[tid + 128] = __expf(cp[tid + 128]);
    if (tid < 16) s_lut[tid] = 1.0f / (1.0f + __expf(-lut[tid]));
    if (tid == 32) {
        float m0 = __expf(mix[0]), m1 = __expf(mix[1]), m2 = __expf(mix[2]);
        float inv = 1.0f / (m0 + m1 + m2);
        s_mix[0] = m0 * inv; s_mix[1] = m1 * inv; s_mix[2] = m2 * inv;
    }
    __syncthreads();

    if (tid < 32) {                              // column sums: lane t sums k = t%4
        float acc = 0.0f;
        #pragma unroll
        for (int i = 0; i < 8; ++i) acc += s_probs_f[tid + 32 * i];
        #pragma unroll
        for (int off = 16; off >= 4; off >>= 1)
            acc += __shfl_down_sync(0xffffffffu, acc, off);
        if (tid < 4) s_inv[tid] = 1.0f / acc;
    }
    __syncthreads();

    s_probs_f[tid]       *= s_inv[tid & 3];      // normalize in place
    s_probs_f[tid + 128] *= s_inv[tid & 3];
    __syncthreads();

    const int r7 = tid & 7;                      // swizzle phase of this row

    int s = 0;                                   // current stage
    unsigned ph = 0;                             // per-stage parity bits
    for (; tile < ntiles; tile += stride) {
        // wait (acquire) for current stage: TMA writes visible to LDS
        mbar_wait_acq(&s_bar[s], (ph >> s) & 1u);
        ph ^= (1u << s);

        // row r at 128B pitch in each half; chunk f at index (f ^ r7)
        const float4* __restrict__ xl = s_x + s * STAGE_F4 + tid * 8;   // f 0..7
        const float4* __restrict__ xh = xl + HALF_F4;                   // f 8..15
        float a0 = 0.0f, a1 = 0.0f, a2 = 0.0f, a3 = 0.0f;
        #pragma unroll
        for (int f = 0; f < 16; ++f) {
            const float4 xv = (f < 8) ? xl[f ^ r7] : xh[(f - 8) ^ r7];
            const float4 p0 = s_probs[4 * f + 0];     // warp-uniform broadcast
            const float4 p1 = s_probs[4 * f + 1];
            const float4 p2 = s_probs[4 * f + 2];
            const float4 p3 = s_probs[4 * f + 3];
            a0 = fmaf(xv.x, p0.x, a0); a1 = fmaf(xv.x, p0.y, a1);
            a2 = fmaf(xv.x, p0.z, a2); a3 = fmaf(xv.x, p0.w, a3);
            a0 = fmaf(xv.y, p1.x, a0); a1 = fmaf(xv.y, p1.y, a1);
            a2 = fmaf(xv.y, p1.z, a2); a3 = fmaf(xv.y, p1.w, a3);
            a0 = fmaf(xv.z, p2.x, a0); a1 = fmaf(xv.z, p2.y, a1);
            a2 = fmaf(xv.z, p2.z, a2); a3 = fmaf(xv.z, p2.w, a3);
            a0 = fmaf(xv.w, p3.x, a0); a1 = fmaf(xv.w, p3.y, a1);
            a2 = fmaf(xv.w, p3.z, a2); a3 = fmaf(xv.w, p3.w, a3);
        }

        const float s0 = a0, s1 = a1, s2 = a2, s3 = a3;

        // addition path
        const float add = s0 + s1 + s2;
        const float ao1 = fminf(fmaxf(add - 2.0f, 0.0f), 1.0f);
        const float ao2 = (add >= 2.0f) ? 1.0f : 0.0f;

        // multilinear contraction over sigmoid(lut)[2,2,2,2]; bit0 -> s, bit1 -> 1-s
        const float w3b = 1.0f - s3;
        const float u0 = s_lut[ 0] * s3 + s_lut[ 1] * w3b;
        const float u1 = s_lut[ 2] * s3 + s_lut[ 3] * w3b;
        const float u2 = s_lut[ 4] * s3 + s_lut[ 5] * w3b;
        const float u3 = s_lut[ 6] * s3 + s_lut[ 7] * w3b;
        const float u4 = s_lut[ 8] * s3 + s_lut[ 9] * w3b;
        const float u5 = s_lut[10] * s3 + s_lut[11] * w3b;
        const float u6 = s_lut[12] * s3 + s_lut[13] * w3b;
        const float u7 = s_lut[14] * s3 + s_lut[15] * w3b;

        const float w2b = 1.0f - s2;
        const float v0 = u0 * s2 + u1 * w2b;
        const float v1 = u2 * s2 + u3 * w2b;
        const float v2 = u4 * s2 + u5 * w2b;
        const float v3 = u6 * s2 + u7 * w2b;

        const float w1b = 1.0f - s1;
        const float r0 = v0 * s1 + v1 * w1b;
        const float r1 = v2 * s1 + v3 * w1b;

        const float lut_out = r0 * s0 + r1 * (1.0f - s0);

        out[tile * TILE_ROWS + tid] = s_mix[0] * lut_out + s_mix[1] * ao1 + s_mix[2] * ao2;

        __syncthreads();   // all reads of stage s done before it is refilled

        // prefetch tile t+2*stride into ring slot (s+2)%NSTAGES
        const int pre = tile + 2 * stride;
        if (tid == 0 && pre < ntiles) {
            int sp = s + 2; if (sp >= NSTAGES) sp -= NSTAGES;
            load_tile(pre, sp);
        }

        if (++s == NSTAGES) s = 0;
    }
}

extern "C" void kernel_launch(void* const* d_in, const int* in_sizes, int n_in,
                              void* d_out, int out_size)
{
    const float* x   = (const float*)d_in[0];   // [B, 64]
    const float* cp  = (const float*)d_in[1];   // [64, 4]
    const float* lut = (const float*)d_in[2];   // 16
    const float* mix = (const float*)d_in[3];   // 3
    float* out = (float*)d_out;

    const int B      = in_sizes[0] / 64;
    const int ntiles = B / TILE_ROWS;           // 8192

    // resolve cuTensorMapEncodeTiled without a -lcuda link dependency
    typedef CUresult (*EncodeFn)(CUtensorMap*, CUtensorMapDataType, cuuint32_t,
                                 void*, const cuuint64_t*, const cuuint64_t*,
                                 const cuuint32_t*, const cuuint32_t*,
                                 CUtensorMapInterleave, CUtensorMapSwizzle,
                                 CUtensorMapL2promotion, CUtensorMapFloatOOBfill);
    static EncodeFn enc = nullptr;              // host-side cache, deterministic
    if (!enc) {
        void* h = dlopen("libcuda.so.1", RTLD_NOW | RTLD_GLOBAL);
        if (!h) h = dlopen("libcuda.so", RTLD_NOW | RTLD_GLOBAL);
        enc = (EncodeFn)dlsym(h, "cuTensorMapEncodeTiled");
    }

    // two half-row descriptors: 32-float inner dim (128B = SW128 atom width),
    // row stride 256B; R half starts 128B into each row.
    cuuint64_t gdim[2]    = {32, (cuuint64_t)B};
    cuuint64_t gstride[1] = {256};
    cuuint32_t box[2]     = {32, TILE_ROWS};
    cuuint32_t estr[2]    = {1, 1};

    CUtensorMap tL, tR;
    enc(&tL, CU_TENSOR_MAP_DATA_TYPE_FLOAT32, 2, (void*)x,
        gdim, gstride, box, estr,
        CU_TENSOR_MAP_INTERLEAVE_NONE, CU_TENSOR_MAP_SWIZZLE_128B,
        CU_TENSOR_MAP_L2_PROMOTION_L2_128B, CU_TENSOR_MAP_FLOAT_OOB_FILL_NONE);
    enc(&tR, CU_TENSOR_MAP_DATA_TYPE_FLOAT32, 2, (void*)((const char*)x + 128),
        gdim, gstride, box, estr,
        CU_TENSOR_MAP_INTERLEAVE_NONE, CU_TENSOR_MAP_SWIZZLE_128B,
        CU_TENSOR_MAP_L2_PROMOTION_L2_128B, CU_TENSOR_MAP_FLOAT_OOB_FILL_NONE);

    // +1KB alignment slack; 3 stages of 32KB; probs + tail
    const int smem_bytes = 1024 + (NSTAGES * STAGE_F4 + 64) * sizeof(float4)
                         + 24 * sizeof(float);

    static bool attr_set = false;               // idempotent, host-side only
    if (!attr_set) {
        cudaFuncSetAttribute(lab_fused_kernel,
                             cudaFuncAttributeMaxDynamicSharedMemorySize, smem_bytes);
        attr_set = true;
    }

    int grid = 296;                             // 2 CTAs/SM x 148 SMs, one wave
    if (grid > ntiles) grid = ntiles;

    lab_fused_kernel<<<grid, NTHREADS, smem_bytes>>>(tL, tR, cp, lut, mix, out, ntiles);
}